// round 6
// baseline (speedup 1.0000x reference)
#include <cuda_runtime.h>

// MyPointConv fused kernel for GB300 (sm_103a) — round 6.
//
// Math (edge_index + self loops; E=1.6M, N=50K):
//   h1 = relu(concat(x_s, pos_s - pos_d) @ W1 + b1)
//      = relu(u[s] - v[d]),  u = x@W1a + pos@W1b + b1,  v = pos@W1b (per node)
//   h2 = relu(h1 @ W2 + b2)
//   agg = segment_max(h2, dst)   (self loops -> nonempty; h2 >= 0)
//   out = agg @ Wg + bg
//
// Pipeline:
//   pre_kernel  : u[N,64], v[N,64]; zero g_agg and g_cnt.
//   hist/scan/place: counting-sort edges by dst -> g_s/g_d (decoded int32).
//                 (max is exactly order-independent -> reordering is safe.)
//   edge_kernel : persistent CTAs; per 128-edge tile: gather relu(u-v),
//                 GEMM2 (64x64, fma.rn.f32x2), per-run max reduction in smem,
//                 ONE atomicMax per (run,col) on int bits (values >= 0).
//   out_kernel  : out = agg@Wg + bg.
//
// edge_index dtype detected at runtime (JAX may canonicalize int64->int32):
// int64 values < 2^31 have zero odd 32-bit words; probe words 1,3,5,7.

#define TILE_E 128
#define NNODES_MAX 50000
#define EMAX 1700000
#define EDGE_GRID 296   // 2 CTAs/SM x 148 SMs

__device__ float g_agg[NNODES_MAX * 64];
__device__ float g_u[NNODES_MAX * 64];
__device__ float g_v[NNODES_MAX * 64];
__device__ int   g_cnt[NNODES_MAX];
__device__ int   g_off[NNODES_MAX];
__device__ int   g_ptr[NNODES_MAX];
__device__ int   g_bsum[256];
__device__ int   g_s[EMAX];
__device__ int   g_d[EMAX];

// ---- f32x2 helpers (sm_100+ packed fp32) ----
typedef unsigned long long u64;

__device__ __forceinline__ void ffma2(u64& acc, u64 ab, u64 w) {
    asm("fma.rn.f32x2 %0, %1, %2, %0;" : "+l"(acc) : "l"(ab), "l"(w));
}
__device__ __forceinline__ u64 bcast2(float m) {
    u64 r;
    asm("mov.b64 %0, {%1, %1};" : "=l"(r) : "f"(m));
    return r;
}
__device__ __forceinline__ u64 pack2(float lo, float hi) {
    u64 r;
    asm("mov.b64 %0, {%1, %2};" : "=l"(r) : "f"(lo), "f"(hi));
    return r;
}
__device__ __forceinline__ void unpack2(u64 v, float& lo, float& hi) {
    asm("mov.b64 {%0, %1}, %2;" : "=f"(lo), "=f"(hi) : "l"(v));
}

__device__ __forceinline__ bool ei_is64(const void* ei_raw) {
    const int* w = (const int*)ei_raw;
    return (w[1] | w[3] | w[5] | w[7]) == 0;
}

// ---------------------------------------------------------------------------
// pre_kernel: u = x@W1[0:32] + pos@W1[32:35] + b1 ; v = pos@W1[32:35]
// Also zeroes g_agg and g_cnt for this CTA's nodes.
// ---------------------------------------------------------------------------
#define SMEM_PRE_BYTES ((35 * 64 + 64 + 128 * 37) * 4)

extern "C" __global__ void __launch_bounds__(256)
pre_kernel(const float* __restrict__ x, const float* __restrict__ pos,
           const float* __restrict__ W1, const float* __restrict__ b1, int N)
{
    extern __shared__ float sm[];
    float* sW1 = sm;               // [35][64]
    float* sb1 = sW1 + 35 * 64;    // [64]
    float* sin = sb1 + 64;         // [128][37]

    const int tid = threadIdx.x;
    const int n0  = blockIdx.x * 128;

    for (int i = tid; i < 35 * 64; i += 256) sW1[i] = W1[i];
    if (tid < 64) sb1[tid] = b1[tid];

    if (tid < 128) {
        int node = n0 + tid;
        if (node < N) g_cnt[node] = 0;
    }
    for (int i = tid; i < 128 * 16; i += 256) {
        int node = n0 + (i >> 4);
        if (node < N)
            ((float4*)(g_agg + node * 64))[i & 15] =
                make_float4(0.f, 0.f, 0.f, 0.f);
    }

    for (int i = tid; i < 128 * 8; i += 256) {
        int e = i >> 3;
        int c = (i & 7) << 2;
        int node = n0 + e;
        float4 v = make_float4(0.f, 0.f, 0.f, 0.f);
        if (node < N) v = *(const float4*)(x + node * 32 + c);
        float* m = sin + e * 37 + c;
        m[0] = v.x; m[1] = v.y; m[2] = v.z; m[3] = v.w;
    }
    for (int i = tid; i < 128 * 3; i += 256) {
        int e  = i / 3;
        int dd = i - e * 3;
        int node = n0 + e;
        sin[e * 37 + 32 + dd] = (node < N) ? pos[node * 3 + dd] : 0.f;
    }
    __syncthreads();

    const int cg = tid & 7;
    const int eg = tid >> 3;
    const int cb = cg * 8;
    const int eb = eg * 4;

    u64 acc[4][4];
    {
        const float2* bp = (const float2*)(sb1 + cb);
        #pragma unroll
        for (int i = 0; i < 4; i++)
            #pragma unroll
            for (int j = 0; j < 4; j++)
                acc[i][j] = pack2(bp[j].x, bp[j].y);
    }

    #pragma unroll 7
    for (int k = 0; k < 35; k++) {
        const ulonglong2* wr = (const ulonglong2*)(sW1 + k * 64 + cb);
        ulonglong2 wa = wr[0];
        ulonglong2 wb = wr[1];
        #pragma unroll
        for (int i = 0; i < 4; i++) {
            u64 m2 = bcast2(sin[(eb + i) * 37 + k]);
            ffma2(acc[i][0], m2, wa.x);
            ffma2(acc[i][1], m2, wa.y);
            ffma2(acc[i][2], m2, wb.x);
            ffma2(acc[i][3], m2, wb.y);
        }
    }
    #pragma unroll
    for (int i = 0; i < 4; i++) {
        int node = n0 + eb + i;
        if (node < N) {
            float r[8];
            #pragma unroll
            for (int j = 0; j < 4; j++) unpack2(acc[i][j], r[2 * j], r[2 * j + 1]);
            float4* o = (float4*)(g_u + node * 64 + cb);
            o[0] = make_float4(r[0], r[1], r[2], r[3]);
            o[1] = make_float4(r[4], r[5], r[6], r[7]);
        }
    }

    // v = pos@W1[32:35]
    #pragma unroll
    for (int i = 0; i < 4; i++)
        #pragma unroll
        for (int j = 0; j < 4; j++)
            acc[i][j] = 0ull;

    #pragma unroll
    for (int k = 32; k < 35; k++) {
        const ulonglong2* wr = (const ulonglong2*)(sW1 + k * 64 + cb);
        ulonglong2 wa = wr[0];
        ulonglong2 wb = wr[1];
        #pragma unroll
        for (int i = 0; i < 4; i++) {
            u64 m2 = bcast2(sin[(eb + i) * 37 + k]);
            ffma2(acc[i][0], m2, wa.x);
            ffma2(acc[i][1], m2, wa.y);
            ffma2(acc[i][2], m2, wb.x);
            ffma2(acc[i][3], m2, wb.y);
        }
    }
    #pragma unroll
    for (int i = 0; i < 4; i++) {
        int node = n0 + eb + i;
        if (node < N) {
            float r[8];
            #pragma unroll
            for (int j = 0; j < 4; j++) unpack2(acc[i][j], r[2 * j], r[2 * j + 1]);
            float4* o = (float4*)(g_v + node * 64 + cb);
            o[0] = make_float4(r[0], r[1], r[2], r[3]);
            o[1] = make_float4(r[4], r[5], r[6], r[7]);
        }
    }
}

// ---------------------------------------------------------------------------
// Counting sort by dst: hist -> scan(3) -> place (decoded src/dst to g_s/g_d)
// ---------------------------------------------------------------------------
extern "C" __global__ void __launch_bounds__(256)
hist_kernel(const void* __restrict__ ei_raw, int E, int Etot)
{
    const bool is64 = ei_is64(ei_raw);
    const int*       ei32 = (const int*)ei_raw;
    const long long* ei64 = (const long long*)ei_raw;
    int i = blockIdx.x * 256 + threadIdx.x;
    if (i >= Etot) return;
    int d;
    if (i < E) d = is64 ? (int)ei64[(long long)E + i] : ei32[E + i];
    else       d = i - E;
    atomicAdd(&g_cnt[d], 1);
}

extern "C" __global__ void __launch_bounds__(256)
scan1_kernel(int N)
{
    __shared__ int s[256];
    const int tid = threadIdx.x;
    int i = blockIdx.x * 256 + tid;
    int v = (i < N) ? g_cnt[i] : 0;
    s[tid] = v;
    __syncthreads();
    #pragma unroll
    for (int o = 1; o < 256; o <<= 1) {
        int t = (tid >= o) ? s[tid - o] : 0;
        __syncthreads();
        s[tid] += t;
        __syncthreads();
    }
    if (i < N) g_off[i] = s[tid] - v;           // exclusive within block
    if (tid == 255) g_bsum[blockIdx.x] = s[255]; // block total
}

extern "C" __global__ void __launch_bounds__(256)
scan2_kernel(int nblk)
{
    __shared__ int s[256];
    const int tid = threadIdx.x;
    int v = (tid < nblk) ? g_bsum[tid] : 0;
    s[tid] = v;
    __syncthreads();
    #pragma unroll
    for (int o = 1; o < 256; o <<= 1) {
        int t = (tid >= o) ? s[tid - o] : 0;
        __syncthreads();
        s[tid] += t;
        __syncthreads();
    }
    g_bsum[tid] = s[tid] - v;                   // exclusive block offsets
}

extern "C" __global__ void __launch_bounds__(256)
scan3_kernel(int N)
{
    int i = blockIdx.x * 256 + threadIdx.x;
    if (i < N) g_ptr[i] = g_off[i] + g_bsum[i >> 8];
}

extern "C" __global__ void __launch_bounds__(256)
place_kernel(const void* __restrict__ ei_raw, int E, int Etot)
{
    const bool is64 = ei_is64(ei_raw);
    const int*       ei32 = (const int*)ei_raw;
    const long long* ei64 = (const long long*)ei_raw;
    int i = blockIdx.x * 256 + threadIdx.x;
    if (i >= Etot) return;
    int s, d;
    if (i < E) {
        if (is64) {
            s = (int)ei64[i];
            d = (int)ei64[(long long)E + i];
        } else {
            s = ei32[i];
            d = ei32[E + i];
        }
    } else {
        s = i - E;   // self loop
        d = s;
    }
    int p = atomicAdd(&g_ptr[d], 1);
    g_s[p] = s;
    g_d[p] = d;
}

// ---------------------------------------------------------------------------
// edge_kernel (persistent): edges pre-sorted by dst. Per 128-edge tile:
//   sh1[e][c] = relu(u[src]-v[dst]); GEMM2 (f32x2); write relu(h2) back to
//   smem; per-dst-run max reduction; one atomicMax per (run, col).
// smem: sW2 64*64 + sb2 64 + sh1 128*65 + idx 256  (~51 KB; 2 CTAs/SM)
// ---------------------------------------------------------------------------
#define SMEM_EDGE_BYTES ((64 * 64 + 64 + 128 * 65) * 4 + 256 * 4)

extern "C" __global__ void __launch_bounds__(256, 2)
edge_kernel(int Etot, const float* __restrict__ W2, const float* __restrict__ b2)
{
    extern __shared__ float sm[];
    float* sW2 = sm;               // [64][64]
    float* sb2 = sW2 + 64 * 64;    // [64]
    float* sh1 = sb2 + 64;         // [128][65]  (reused as h2 after GEMM)
    int*  ssrc = (int*)(sh1 + 128 * 65);
    int*  sdst = ssrc + 128;

    const int tid = threadIdx.x;

    for (int i = tid; i < 64 * 64; i += 256) sW2[i] = W2[i];
    if (tid < 64) sb2[tid] = b2[tid];
    __syncthreads();

    const int cg = tid & 7;
    const int eg = tid >> 3;
    const int cb = cg * 8;
    const int eb = eg * 4;

    u64 b2p[4];
    {
        const float2* bp = (const float2*)(sb2 + cb);
        #pragma unroll
        for (int j = 0; j < 4; j++) b2p[j] = pack2(bp[j].x, bp[j].y);
    }

    const int ntiles = (Etot + TILE_E - 1) / TILE_E;

    for (int t = blockIdx.x; t < ntiles; t += EDGE_GRID) {
        const int e0 = t * TILE_E;

        if (tid < TILE_E) {
            int idx = e0 + tid;
            int s = 0, d = -1;
            if (idx < Etot) { s = g_s[idx]; d = g_d[idx]; }
            ssrc[tid] = s;
            sdst[tid] = d;
        }
        __syncthreads();

        // Gather + h1 = relu(u[s] - v[d]) into smem.
        // dst sorted -> v[d] rows are run-local (L1 hits).
        for (int i = tid; i < TILE_E * 16; i += 256) {
            int e = i >> 4;
            int c = (i & 15) << 2;
            float4 hv = make_float4(0.f, 0.f, 0.f, 0.f);
            int d = sdst[e];
            if (d >= 0) {
                float4 uv = *(const float4*)(g_u + ssrc[e] * 64 + c);
                float4 vv = *(const float4*)(g_v + d * 64 + c);
                hv.x = fmaxf(uv.x - vv.x, 0.f);
                hv.y = fmaxf(uv.y - vv.y, 0.f);
                hv.z = fmaxf(uv.z - vv.z, 0.f);
                hv.w = fmaxf(uv.w - vv.w, 0.f);
            }
            float* p = sh1 + e * 65 + c;
            p[0] = hv.x; p[1] = hv.y; p[2] = hv.z; p[3] = hv.w;
        }
        __syncthreads();

        // GEMM2: [128,64] @ [64,64] + b2
        u64 acc[4][4];
        #pragma unroll
        for (int i = 0; i < 4; i++) {
            acc[i][0] = b2p[0]; acc[i][1] = b2p[1];
            acc[i][2] = b2p[2]; acc[i][3] = b2p[3];
        }

        #pragma unroll 8
        for (int k = 0; k < 64; k++) {
            const ulonglong2* wr = (const ulonglong2*)(sW2 + k * 64 + cb);
            ulonglong2 wa = wr[0];
            ulonglong2 wb = wr[1];
            #pragma unroll
            for (int i = 0; i < 4; i++) {
                u64 m2 = bcast2(sh1[(eb + i) * 65 + k]);
                ffma2(acc[i][0], m2, wa.x);
                ffma2(acc[i][1], m2, wa.y);
                ffma2(acc[i][2], m2, wb.x);
                ffma2(acc[i][3], m2, wb.y);
            }
        }
        __syncthreads();   // all sh1 reads complete before overwrite

        // Write relu(h2) back into sh1 (now "sh2").
        #pragma unroll
        for (int i = 0; i < 4; i++) {
            float* dstp = sh1 + (eb + i) * 65 + cb;
            #pragma unroll
            for (int j = 0; j < 4; j++) {
                float lo, hi;
                unpack2(acc[i][j], lo, hi);
                dstp[2 * j]     = fmaxf(lo, 0.f);
                dstp[2 * j + 1] = fmaxf(hi, 0.f);
            }
        }
        __syncthreads();

        // Per-run max reduction: thread (e, col-quad) acts only if e is the
        // first edge of its dst run in this tile; reduces the run, then one
        // filtered atomicMax per col (int-bit max exact for floats >= 0).
        for (int i = tid; i < TILE_E * 16; i += 256) {
            int e = i >> 4;
            int d = sdst[e];
            if (d < 0) continue;
            if (e > 0 && sdst[e - 1] == d) continue;   // not a run head
            int c = (i & 15) << 2;
            const float* p = sh1 + e * 65 + c;
            float m0 = p[0], m1 = p[1], m2 = p[2], m3 = p[3];
            int ee = e + 1;
            while (ee < TILE_E && sdst[ee] == d) {
                const float* q = sh1 + ee * 65 + c;
                m0 = fmaxf(m0, q[0]);
                m1 = fmaxf(m1, q[1]);
                m2 = fmaxf(m2, q[2]);
                m3 = fmaxf(m3, q[3]);
                ee++;
            }
            int* base = (int*)(g_agg + d * 64 + c);
            if (m0 > 0.f) atomicMax(base + 0, __float_as_int(m0));
            if (m1 > 0.f) atomicMax(base + 1, __float_as_int(m1));
            if (m2 > 0.f) atomicMax(base + 2, __float_as_int(m2));
            if (m3 > 0.f) atomicMax(base + 3, __float_as_int(m3));
        }

        __syncthreads();   // protect smem before next tile
    }
}

// ---------------------------------------------------------------------------
// out = agg @ Wg + bg ; 64 nodes/CTA, 256 threads (16 ng x 16 cg)
// ---------------------------------------------------------------------------
#define SMEM_OUT_BYTES ((64 * 128 + 64 * 65) * 4)

extern "C" __global__ void __launch_bounds__(256)
out_kernel(const float* __restrict__ Wg, const float* __restrict__ bg,
           float* __restrict__ out, int N)
{
    extern __shared__ float sm[];
    float* sWg = sm;              // [64][128]
    float* sa  = sWg + 64 * 128;  // [64][65]

    const int tid = threadIdx.x;
    for (int i = tid; i < 64 * 128; i += 256) sWg[i] = Wg[i];

    const int n0 = blockIdx.x * 64;
    for (int i = tid; i < 64 * 16; i += 256) {
        int n = i >> 4;
        int c = (i & 15) << 2;
        float4 v = make_float4(0.f, 0.f, 0.f, 0.f);
        if (n0 + n < N) v = *(const float4*)(g_agg + (n0 + n) * 64 + c);
        float* a = sa + n * 65 + c;
        a[0] = v.x; a[1] = v.y; a[2] = v.z; a[3] = v.w;
    }
    __syncthreads();

    const int cg = tid & 15;
    const int ng = tid >> 4;
    const int cb = cg * 8;
    const int nb = ng * 4;

    u64 acc[4][4];
    {
        u64 b01 = pack2(bg[cb],     bg[cb + 1]);
        u64 b23 = pack2(bg[cb + 2], bg[cb + 3]);
        u64 b45 = pack2(bg[cb + 4], bg[cb + 5]);
        u64 b67 = pack2(bg[cb + 6], bg[cb + 7]);
        #pragma unroll
        for (int i = 0; i < 4; i++) {
            acc[i][0] = b01; acc[i][1] = b23;
            acc[i][2] = b45; acc[i][3] = b67;
        }
    }

    #pragma unroll 8
    for (int k = 0; k < 64; k++) {
        const ulonglong2* wr = (const ulonglong2*)(sWg + k * 128 + cb);
        ulonglong2 wa = wr[0];
        ulonglong2 wb = wr[1];
        #pragma unroll
        for (int i = 0; i < 4; i++) {
            u64 a2 = bcast2(sa[(nb + i) * 65 + k]);
            ffma2(acc[i][0], a2, wa.x);
            ffma2(acc[i][1], a2, wa.y);
            ffma2(acc[i][2], a2, wb.x);
            ffma2(acc[i][3], a2, wb.y);
        }
    }

    #pragma unroll
    for (int i = 0; i < 4; i++) {
        int n = n0 + nb + i;
        if (n < N) {
            float r[8];
            #pragma unroll
            for (int j = 0; j < 4; j++) unpack2(acc[i][j], r[2 * j], r[2 * j + 1]);
            float4* o = (float4*)(out + (long long)n * 128 + cb);
            o[0] = make_float4(r[0], r[1], r[2], r[3]);
            o[1] = make_float4(r[4], r[5], r[6], r[7]);
        }
    }
}

extern "C" void kernel_launch(void* const* d_in, const int* in_sizes, int n_in,
                              void* d_out, int out_size)
{
    const float* x   = (const float*)d_in[0];
    const float* pos = (const float*)d_in[1];
    const void*  ei  = d_in[2];                 // int32 or int64, device-detected
    const float* W1  = (const float*)d_in[3];
    const float* b1  = (const float*)d_in[4];
    const float* W2  = (const float*)d_in[5];
    const float* b2  = (const float*)d_in[6];
    const float* Wg  = (const float*)d_in[7];
    const float* bg  = (const float*)d_in[8];
    float*       out = (float*)d_out;

    const int N    = in_sizes[0] / 32;
    const int E    = in_sizes[2] / 2;
    const int Etot = E + N;

    cudaFuncSetAttribute(pre_kernel,
                         cudaFuncAttributeMaxDynamicSharedMemorySize,
                         SMEM_PRE_BYTES);
    cudaFuncSetAttribute(edge_kernel,
                         cudaFuncAttributeMaxDynamicSharedMemorySize,
                         SMEM_EDGE_BYTES);
    cudaFuncSetAttribute(out_kernel,
                         cudaFuncAttributeMaxDynamicSharedMemorySize,
                         SMEM_OUT_BYTES);

    const int eblk = (Etot + 255) / 256;
    const int nblk = (N + 255) / 256;   // <= 256 required by scan2 (N <= 65536)

    pre_kernel<<<(N + 127) / 128, 256, SMEM_PRE_BYTES>>>(x, pos, W1, b1, N);
    hist_kernel<<<eblk, 256>>>(ei, E, Etot);
    scan1_kernel<<<nblk, 256>>>(N);
    scan2_kernel<<<1, 256>>>(nblk);
    scan3_kernel<<<nblk, 256>>>(N);
    place_kernel<<<eblk, 256>>>(ei, E, Etot);
    edge_kernel<<<EDGE_GRID, 256, SMEM_EDGE_BYTES>>>(Etot, W2, b2);
    out_kernel<<<(N + 63) / 64, 256, SMEM_OUT_BYTES>>>(Wg, bg, out, N);
}

// round 15
// speedup vs baseline: 1.3737x; 1.3737x over previous
#include <cuda_runtime.h>

// MyPointConv fused kernel for GB300 (sm_103a) — round 15 (R8 design, resubmit).
//
// Math (edge_index + self loops; E=1.6M, N=50K):
//   h1 = relu(concat(x_s, pos_s - pos_d) @ W1 + b1)
//      = relu(u[s] - v[d]),  u = x@W1a + pos@W1b + b1,  v = pos@W1b (per node)
//   h2 = relu(h1 @ W2 + b2)
//   agg = segment_max(h2, dst)   (self loops -> nonempty; h2 >= 0)
//   out = agg @ Wg + bg
//
// Launch order (5 launches so ncu -s5 lands on edge_kernel):
//   0: pre_kernel   u/v, zero g_agg, dst histogram (g_cnt; zeroed by prev scan)
//   1: scan_kernel  exclusive scan g_cnt -> g_ptr; rezero g_cnt
//   2: place_kernel counting-sort placement -> g_s/g_d (decoded int32)
//   3: edge_kernel  persistent; gather relu(u-v), GEMM2 f32x2, run-max, atomics
//   4: out_kernel   out = agg@Wg + bg
//
// Edge dtype sniffed on device (JAX may canonicalize int64->int32).
// All math exact fp32; reordering is safe because max is order-independent.

#define TILE_E 128
#define NNODES_MAX 50000
#define EMAX 1700000
#define EDGE_GRID 444   // 3 CTAs/SM x 148 SMs
#define H1S 68          // sh1 row stride (floats): 272B, 16B-aligned

__device__ float g_agg[NNODES_MAX * 64];
__device__ float g_u[NNODES_MAX * 64];
__device__ float g_v[NNODES_MAX * 64];
__device__ int   g_cnt[NNODES_MAX];   // zero-init; re-zeroed by scan_kernel
__device__ int   g_ptr[NNODES_MAX];
__device__ int   g_s[EMAX];
__device__ int   g_d[EMAX];

typedef unsigned long long u64;

__device__ __forceinline__ void ffma2(u64& acc, u64 ab, u64 w) {
    asm("fma.rn.f32x2 %0, %1, %2, %0;" : "+l"(acc) : "l"(ab), "l"(w));
}
__device__ __forceinline__ u64 bcast2(float m) {
    u64 r;
    asm("mov.b64 %0, {%1, %1};" : "=l"(r) : "f"(m));
    return r;
}
__device__ __forceinline__ u64 pack2(float lo, float hi) {
    u64 r;
    asm("mov.b64 %0, {%1, %2};" : "=l"(r) : "f"(lo), "f"(hi));
    return r;
}
__device__ __forceinline__ void unpack2(u64 v, float& lo, float& hi) {
    asm("mov.b64 {%0, %1}, %2;" : "=f"(lo), "=f"(hi) : "l"(v));
}
__device__ __forceinline__ bool ei_is64(const void* ei_raw) {
    const int* w = (const int*)ei_raw;
    return (w[1] | w[3] | w[5] | w[7]) == 0;
}

// ---------------------------------------------------------------------------
// pre_kernel: u/v per node, zero g_agg, and dst histogram into g_cnt.
// (g_cnt is zero at call time: static zero-init on call 0, re-zeroed by
//  scan_kernel each call -> deterministic across graph replays.)
// ---------------------------------------------------------------------------
#define SMEM_PRE_BYTES ((35 * 64 + 64 + 128 * 37) * 4)

extern "C" __global__ void __launch_bounds__(256)
pre_kernel(const float* __restrict__ x, const float* __restrict__ pos,
           const float* __restrict__ W1, const float* __restrict__ b1,
           const void* __restrict__ ei_raw, int E, int Etot, int N)
{
    extern __shared__ float sm[];
    float* sW1 = sm;               // [35][64]
    float* sb1 = sW1 + 35 * 64;    // [64]
    float* sin = sb1 + 64;         // [128][37]

    const int tid = threadIdx.x;
    const int n0  = blockIdx.x * 128;

    for (int i = tid; i < 35 * 64; i += 256) sW1[i] = W1[i];
    if (tid < 64) sb1[tid] = b1[tid];

    // Zero g_agg rows for this CTA's nodes.
    for (int i = tid; i < 128 * 16; i += 256) {
        int node = n0 + (i >> 4);
        if (node < N)
            ((float4*)(g_agg + node * 64))[i & 15] =
                make_float4(0.f, 0.f, 0.f, 0.f);
    }

    // dst histogram (grid-stride over all edges incl. self loops).
    {
        const bool is64 = ei_is64(ei_raw);
        const int*       ei32 = (const int*)ei_raw;
        const long long* ei64 = (const long long*)ei_raw;
        for (int i = blockIdx.x * 256 + tid; i < Etot; i += gridDim.x * 256) {
            int d;
            if (i < E) d = is64 ? (int)ei64[(long long)E + i] : ei32[E + i];
            else       d = i - E;
            atomicAdd(&g_cnt[d], 1);
        }
    }

    // Stage node inputs.
    for (int i = tid; i < 128 * 8; i += 256) {
        int e = i >> 3;
        int c = (i & 7) << 2;
        int node = n0 + e;
        float4 v = make_float4(0.f, 0.f, 0.f, 0.f);
        if (node < N) v = *(const float4*)(x + node * 32 + c);
        float* m = sin + e * 37 + c;
        m[0] = v.x; m[1] = v.y; m[2] = v.z; m[3] = v.w;
    }
    for (int i = tid; i < 128 * 3; i += 256) {
        int e  = i / 3;
        int dd = i - e * 3;
        int node = n0 + e;
        sin[e * 37 + 32 + dd] = (node < N) ? pos[node * 3 + dd] : 0.f;
    }
    __syncthreads();

    const int cg = tid & 7;
    const int eg = tid >> 3;
    const int cb = cg * 8;
    const int eb = eg * 4;

    u64 acc[4][4];
    {
        const float2* bp = (const float2*)(sb1 + cb);
        #pragma unroll
        for (int i = 0; i < 4; i++)
            #pragma unroll
            for (int j = 0; j < 4; j++)
                acc[i][j] = pack2(bp[j].x, bp[j].y);
    }

    #pragma unroll 7
    for (int k = 0; k < 35; k++) {
        const ulonglong2* wr = (const ulonglong2*)(sW1 + k * 64 + cb);
        ulonglong2 wa = wr[0];
        ulonglong2 wb = wr[1];
        #pragma unroll
        for (int i = 0; i < 4; i++) {
            u64 m2 = bcast2(sin[(eb + i) * 37 + k]);
            ffma2(acc[i][0], m2, wa.x);
            ffma2(acc[i][1], m2, wa.y);
            ffma2(acc[i][2], m2, wb.x);
            ffma2(acc[i][3], m2, wb.y);
        }
    }
    #pragma unroll
    for (int i = 0; i < 4; i++) {
        int node = n0 + eb + i;
        if (node < N) {
            float r[8];
            #pragma unroll
            for (int j = 0; j < 4; j++) unpack2(acc[i][j], r[2 * j], r[2 * j + 1]);
            float4* o = (float4*)(g_u + node * 64 + cb);
            o[0] = make_float4(r[0], r[1], r[2], r[3]);
            o[1] = make_float4(r[4], r[5], r[6], r[7]);
        }
    }

    // v = pos@W1[32:35]
    #pragma unroll
    for (int i = 0; i < 4; i++)
        #pragma unroll
        for (int j = 0; j < 4; j++)
            acc[i][j] = 0ull;

    #pragma unroll
    for (int k = 32; k < 35; k++) {
        const ulonglong2* wr = (const ulonglong2*)(sW1 + k * 64 + cb);
        ulonglong2 wa = wr[0];
        ulonglong2 wb = wr[1];
        #pragma unroll
        for (int i = 0; i < 4; i++) {
            u64 m2 = bcast2(sin[(eb + i) * 37 + k]);
            ffma2(acc[i][0], m2, wa.x);
            ffma2(acc[i][1], m2, wa.y);
            ffma2(acc[i][2], m2, wb.x);
            ffma2(acc[i][3], m2, wb.y);
        }
    }
    #pragma unroll
    for (int i = 0; i < 4; i++) {
        int node = n0 + eb + i;
        if (node < N) {
            float r[8];
            #pragma unroll
            for (int j = 0; j < 4; j++) unpack2(acc[i][j], r[2 * j], r[2 * j + 1]);
            float4* o = (float4*)(g_v + node * 64 + cb);
            o[0] = make_float4(r[0], r[1], r[2], r[3]);
            o[1] = make_float4(r[4], r[5], r[6], r[7]);
        }
    }
}

// ---------------------------------------------------------------------------
// scan_kernel: single-CTA exclusive scan of g_cnt[0..N) -> g_ptr; rezero g_cnt.
// ---------------------------------------------------------------------------
extern "C" __global__ void __launch_bounds__(1024)
scan_kernel(int N)
{
    __shared__ int wsum[32];
    __shared__ int s_carry;
    const int tid  = threadIdx.x;
    const int lane = tid & 31;
    const int wid  = tid >> 5;
    if (tid == 0) s_carry = 0;
    __syncthreads();

    for (int base = 0; base < N; base += 1024) {
        int i = base + tid;
        int v = (i < N) ? g_cnt[i] : 0;
        if (i < N) g_cnt[i] = 0;                 // rezero for next call's hist

        int x = v;
        #pragma unroll
        for (int o = 1; o < 32; o <<= 1) {
            int y = __shfl_up_sync(0xffffffffu, x, o);
            if (lane >= o) x += y;
        }
        if (lane == 31) wsum[wid] = x;
        __syncthreads();
        if (wid == 0) {
            int t = wsum[lane];
            #pragma unroll
            for (int o = 1; o < 32; o <<= 1) {
                int y = __shfl_up_sync(0xffffffffu, t, o);
                if (lane >= o) t += y;
            }
            wsum[lane] = t;                      // inclusive warp totals
        }
        __syncthreads();
        int warp_excl = (wid == 0) ? 0 : wsum[wid - 1];
        if (i < N) g_ptr[i] = s_carry + warp_excl + x - v;
        __syncthreads();
        if (tid == 0) s_carry += wsum[31];
        __syncthreads();
    }
}

// ---------------------------------------------------------------------------
// place_kernel: scatter edges into dst-sorted order (decoded int32).
// ---------------------------------------------------------------------------
extern "C" __global__ void __launch_bounds__(256)
place_kernel(const void* __restrict__ ei_raw, int E, int Etot)
{
    const bool is64 = ei_is64(ei_raw);
    const int*       ei32 = (const int*)ei_raw;
    const long long* ei64 = (const long long*)ei_raw;
    int i = blockIdx.x * 256 + threadIdx.x;
    if (i >= Etot) return;
    int s, d;
    if (i < E) {
        if (is64) {
            s = (int)ei64[i];
            d = (int)ei64[(long long)E + i];
        } else {
            s = ei32[i];
            d = ei32[E + i];
        }
    } else {
        s = i - E;   // self loop
        d = s;
    }
    int p = atomicAdd(&g_ptr[d], 1);
    g_s[p] = s;
    g_d[p] = d;
}

// ---------------------------------------------------------------------------
// edge_kernel (persistent, 3 CTAs/SM): edges pre-sorted by dst.
// Weights split: sWa[k][cg][4] = cols 8cg..8cg+3, sWb[k][cg][4] = 8cg+4..8cg+7
// so each warp's weight LDS.128 covers one dense 128B line (1 wavefront).
// Edge operands read as LDS.128 (4 k at once): 4x fewer edge-operand LDS.
// smem: sWa 2048 + sWb 2048 + sb2 64 + sh1 128*68 + idx 256  (~52 KB)
// ---------------------------------------------------------------------------
#define SMEM_EDGE_BYTES ((2048 + 2048 + 64 + 128 * H1S) * 4 + 256 * 4)

extern "C" __global__ void __launch_bounds__(256, 3)
edge_kernel(int Etot, const float* __restrict__ W2, const float* __restrict__ b2)
{
    extern __shared__ float sm[];
    float* sWa = sm;               // [64][8][4]
    float* sWb = sWa + 2048;       // [64][8][4]
    float* sb2 = sWb + 2048;       // [64]
    float* sh1 = sb2 + 64;         // [128][H1S]  (h1, then reused as h2)
    int*  ssrc = (int*)(sh1 + 128 * H1S);
    int*  sdst = ssrc + 128;

    const int tid = threadIdx.x;

    // Stage W2 in split layout, b2.
    for (int i = tid; i < 64 * 64; i += 256) {
        int k = i >> 6, col = i & 63;
        int c = col >> 3, r = col & 7;
        float w = W2[k * 64 + col];
        if (r < 4) sWa[k * 32 + c * 4 + r]       = w;
        else       sWb[k * 32 + c * 4 + (r - 4)] = w;
    }
    if (tid < 64) sb2[tid] = b2[tid];
    __syncthreads();

    const int cg = tid & 7;
    const int eg = tid >> 3;
    const int cb = cg * 8;
    const int eb = eg * 4;

    u64 b2p[4];
    {
        const float2* bp = (const float2*)(sb2 + cb);
        #pragma unroll
        for (int j = 0; j < 4; j++) b2p[j] = pack2(bp[j].x, bp[j].y);
    }

    const int ntiles = (Etot + TILE_E - 1) / TILE_E;

    for (int t = blockIdx.x; t < ntiles; t += EDGE_GRID) {
        const int e0 = t * TILE_E;

        if (tid < TILE_E) {
            int idx = e0 + tid;
            int s = 0, d = -1;
            if (idx < Etot) { s = g_s[idx]; d = g_d[idx]; }
            ssrc[tid] = s;
            sdst[tid] = d;
        }
        __syncthreads();

        // Gather + h1 = relu(u[s] - v[d]) into smem.
        #pragma unroll 4
        for (int it = 0; it < 8; it++) {
            int i = tid + it * 256;
            int e = i >> 4;
            int c = (i & 15) << 2;
            float4 hv = make_float4(0.f, 0.f, 0.f, 0.f);
            int d = sdst[e];
            if (d >= 0) {
                float4 uv = *(const float4*)(g_u + ssrc[e] * 64 + c);
                float4 vv = *(const float4*)(g_v + d * 64 + c);
                hv.x = fmaxf(uv.x - vv.x, 0.f);
                hv.y = fmaxf(uv.y - vv.y, 0.f);
                hv.z = fmaxf(uv.z - vv.z, 0.f);
                hv.w = fmaxf(uv.w - vv.w, 0.f);
            }
            *(float4*)(sh1 + e * H1S + c) = hv;
        }
        __syncthreads();

        // GEMM2: [128,64] @ [64,64] + b2 (f32x2).
        // Edge operands loaded 4-k at a time via LDS.128.
        u64 acc[4][4];
        #pragma unroll
        for (int i = 0; i < 4; i++) {
            acc[i][0] = b2p[0]; acc[i][1] = b2p[1];
            acc[i][2] = b2p[2]; acc[i][3] = b2p[3];
        }

        #pragma unroll 2
        for (int kb = 0; kb < 64; kb += 4) {
            float mrow[4][4];
            #pragma unroll
            for (int i = 0; i < 4; i++) {
                float4 t4 = *(const float4*)(sh1 + (eb + i) * H1S + kb);
                mrow[i][0] = t4.x; mrow[i][1] = t4.y;
                mrow[i][2] = t4.z; mrow[i][3] = t4.w;
            }
            #pragma unroll
            for (int kk = 0; kk < 4; kk++) {
                int k = kb + kk;
                ulonglong2 wa = *(const ulonglong2*)(sWa + k * 32 + cg * 4);
                ulonglong2 wb = *(const ulonglong2*)(sWb + k * 32 + cg * 4);
                #pragma unroll
                for (int i = 0; i < 4; i++) {
                    u64 m2 = bcast2(mrow[i][kk]);
                    ffma2(acc[i][0], m2, wa.x);
                    ffma2(acc[i][1], m2, wa.y);
                    ffma2(acc[i][2], m2, wb.x);
                    ffma2(acc[i][3], m2, wb.y);
                }
            }
        }
        __syncthreads();   // all sh1 reads complete before overwrite

        // Write relu(h2) back into sh1 (now h2), vectorized.
        #pragma unroll
        for (int i = 0; i < 4; i++) {
            float r[8];
            #pragma unroll
            for (int j = 0; j < 4; j++) {
                float lo, hi;
                unpack2(acc[i][j], lo, hi);
                r[2 * j]     = fmaxf(lo, 0.f);
                r[2 * j + 1] = fmaxf(hi, 0.f);
            }
            float4* dstp = (float4*)(sh1 + (eb + i) * H1S + cb);
            dstp[0] = make_float4(r[0], r[1], r[2], r[3]);
            dstp[1] = make_float4(r[4], r[5], r[6], r[7]);
        }
        __syncthreads();

        // Per-run max reduction (dst-sorted): run-head threads reduce the run,
        // one filtered atomicMax per (run, col); int-bit max exact for >= 0.
        for (int i = tid; i < TILE_E * 16; i += 256) {
            int e = i >> 4;
            int d = sdst[e];
            if (d < 0) continue;
            if (e > 0 && sdst[e - 1] == d) continue;   // not a run head
            int c = (i & 15) << 2;
            const float* p = sh1 + e * H1S + c;
            float m0 = p[0], m1 = p[1], m2 = p[2], m3 = p[3];
            int ee = e + 1;
            while (ee < TILE_E && sdst[ee] == d) {
                const float* q = sh1 + ee * H1S + c;
                m0 = fmaxf(m0, q[0]);
                m1 = fmaxf(m1, q[1]);
                m2 = fmaxf(m2, q[2]);
                m3 = fmaxf(m3, q[3]);
                ee++;
            }
            int* base = (int*)(g_agg + d * 64 + c);
            if (m0 > 0.f) atomicMax(base + 0, __float_as_int(m0));
            if (m1 > 0.f) atomicMax(base + 1, __float_as_int(m1));
            if (m2 > 0.f) atomicMax(base + 2, __float_as_int(m2));
            if (m3 > 0.f) atomicMax(base + 3, __float_as_int(m3));
        }

        __syncthreads();   // protect smem before next tile
    }
}

// ---------------------------------------------------------------------------
// out = agg @ Wg + bg ; 64 nodes/CTA, 256 threads (16 ng x 16 cg)
// ---------------------------------------------------------------------------
#define SMEM_OUT_BYTES ((64 * 128 + 64 * 65) * 4)

extern "C" __global__ void __launch_bounds__(256)
out_kernel(const float* __restrict__ Wg, const float* __restrict__ bg,
           float* __restrict__ out, int N)
{
    extern __shared__ float sm[];
    float* sWg = sm;              // [64][128]
    float* sa  = sWg + 64 * 128;  // [64][65]

    const int tid = threadIdx.x;
    for (int i = tid; i < 64 * 128; i += 256) sWg[i] = Wg[i];

    const int n0 = blockIdx.x * 64;
    for (int i = tid; i < 64 * 16; i += 256) {
        int n = i >> 4;
        int c = (i & 15) << 2;
        float4 v = make_float4(0.f, 0.f, 0.f, 0.f);
        if (n0 + n < N) v = *(const float4*)(g_agg + (n0 + n) * 64 + c);
        float* a = sa + n * 65 + c;
        a[0] = v.x; a[1] = v.y; a[2] = v.z; a[3] = v.w;
    }
    __syncthreads();

    const int cg = tid & 15;
    const int ng = tid >> 4;
    const int cb = cg * 8;
    const int nb = ng * 4;

    u64 acc[4][4];
    {
        u64 b01 = pack2(bg[cb],     bg[cb + 1]);
        u64 b23 = pack2(bg[cb + 2], bg[cb + 3]);
        u64 b45 = pack2(bg[cb + 4], bg[cb + 5]);
        u64 b67 = pack2(bg[cb + 6], bg[cb + 7]);
        #pragma unroll
        for (int i = 0; i < 4; i++) {
            acc[i][0] = b01; acc[i][1] = b23;
            acc[i][2] = b45; acc[i][3] = b67;
        }
    }

    #pragma unroll 8
    for (int k = 0; k < 64; k++) {
        const ulonglong2* wr = (const ulonglong2*)(sWg + k * 128 + cb);
        ulonglong2 wa = wr[0];
        ulonglong2 wb = wr[1];
        #pragma unroll
        for (int i = 0; i < 4; i++) {
            u64 a2 = bcast2(sa[(nb + i) * 65 + k]);
            ffma2(acc[i][0], a2, wa.x);
            ffma2(acc[i][1], a2, wa.y);
            ffma2(acc[i][2], a2, wb.x);
            ffma2(acc[i][3], a2, wb.y);
        }
    }

    #pragma unroll
    for (int i = 0; i < 4; i++) {
        int n = n0 + nb + i;
        if (n < N) {
            float r[8];
            #pragma unroll
            for (int j = 0; j < 4; j++) unpack2(acc[i][j], r[2 * j], r[2 * j + 1]);
            float4* o = (float4*)(out + (long long)n * 128 + cb);
            o[0] = make_float4(r[0], r[1], r[2], r[3]);
            o[1] = make_float4(r[4], r[5], r[6], r[7]);
        }
    }
}

extern "C" void kernel_launch(void* const* d_in, const int* in_sizes, int n_in,
                              void* d_out, int out_size)
{
    const float* x   = (const float*)d_in[0];
    const float* pos = (const float*)d_in[1];
    const void*  ei  = d_in[2];                 // int32 or int64, device-detected
    const float* W1  = (const float*)d_in[3];
    const float* b1  = (const float*)d_in[4];
    const float* W2  = (const float*)d_in[5];
    const float* b2  = (const float*)d_in[6];
    const float* Wg  = (const float*)d_in[7];
    const float* bg  = (const float*)d_in[8];
    float*       out = (float*)d_out;

    const int N    = in_sizes[0] / 32;
    const int E    = in_sizes[2] / 2;
    const int Etot = E + N;

    cudaFuncSetAttribute(pre_kernel,
                         cudaFuncAttributeMaxDynamicSharedMemorySize,
                         SMEM_PRE_BYTES);
    cudaFuncSetAttribute(edge_kernel,
                         cudaFuncAttributeMaxDynamicSharedMemorySize,
                         SMEM_EDGE_BYTES);
    cudaFuncSetAttribute(out_kernel,
                         cudaFuncAttributeMaxDynamicSharedMemorySize,
                         SMEM_OUT_BYTES);

    pre_kernel<<<(N + 127) / 128, 256, SMEM_PRE_BYTES>>>(
        x, pos, W1, b1, ei, E, Etot, N);
    scan_kernel<<<1, 1024>>>(N);
    place_kernel<<<(Etot + 255) / 256, 256>>>(ei, E, Etot);
    edge_kernel<<<EDGE_GRID, 256, SMEM_EDGE_BYTES>>>(Etot, W2, b2);
    out_kernel<<<(N + 63) / 64, 256, SMEM_OUT_BYTES>>>(Wg, bg, out, N);
}